// round 1
// baseline (speedup 1.0000x reference)
#include <cuda_runtime.h>
#include <math.h>

// Problem constants (fixed by setup_inputs)
#define V   262144          // 64*64*64
#define NK  9
#define EPSV 1e-5f

// ---------------- scratch (__device__ globals; no allocation) ----------------
__device__ float g_ft[V * 8];        // f transposed to [D][W][H][C]  (8 MB)
__device__ float g_off[18 * V];      // offset conv output, [ch][voxel] (18 MB)
__device__ float g_conv[16 * V];     // dcn conv output pre-GN, [co][voxel] (16 MB)
__device__ float g_bnsum[18];
__device__ float g_bnsq[18];
__device__ float g_bns[18];          // folded BN scale
__device__ float g_bnt[18];          // folded BN shift
__device__ float g_gsum[4];
__device__ float g_gsq[4];
__device__ float g_gns[16];          // folded GN scale per out channel
__device__ float g_gnt[16];          // folded GN shift per out channel

// ---------------- kernel 1: transpose f [8][V] -> [V][8], zero stats ----------------
__global__ void k_transpose(const float* __restrict__ f) {
    int tid = threadIdx.x;
    if (blockIdx.x == 0 && tid < 22) {
        if (tid < 18) { g_bnsum[tid] = 0.f; g_bnsq[tid] = 0.f; }
        else          { g_gsum[tid - 18] = 0.f; g_gsq[tid - 18] = 0.f; }
    }
    int v = blockIdx.x * blockDim.x + tid;
    if (v >= V) return;
    float4 a, b;
    a.x = f[0 * V + v]; a.y = f[1 * V + v]; a.z = f[2 * V + v]; a.w = f[3 * V + v];
    b.x = f[4 * V + v]; b.y = f[5 * V + v]; b.z = f[6 * V + v]; b.w = f[7 * V + v];
    float4* dst = reinterpret_cast<float4*>(g_ft);
    dst[v * 2 + 0] = a;
    dst[v * 2 + 1] = b;
}

// ---------------- kernel 2: offset conv3d (18 out ch, 3x3x3, pad 1) + BN partial stats ----------------
__global__ void k_conv_off(const float* __restrict__ offw, const float* __restrict__ offb) {
    __shared__ float sw[18 * 8 * 27];   // 3888 floats
    int tid = threadIdx.x;
    for (int i = tid; i < 3888; i += 256) sw[i] = offw[i];
    __syncthreads();

    int v = blockIdx.x * 256 + tid;
    int h = v & 63, w = (v >> 6) & 63, d = v >> 12;

    float acc[18];
#pragma unroll
    for (int j = 0; j < 18; j++) acc[j] = __ldg(&offb[j]);

    for (int dz = 0; dz < 3; dz++) {
        int zz = d + dz - 1;
        for (int dy = 0; dy < 3; dy++) {
            int yy = w + dy - 1;
            for (int dx = 0; dx < 3; dx++) {
                int xx = h + dx - 1;
                float in8[8];
                if ((unsigned)zz < 64u && (unsigned)yy < 64u && (unsigned)xx < 64u) {
                    const float4* p = reinterpret_cast<const float4*>(
                        &g_ft[((((zz << 6) + yy) << 6) + xx) * 8]);
                    float4 a = p[0], b = p[1];
                    in8[0] = a.x; in8[1] = a.y; in8[2] = a.z; in8[3] = a.w;
                    in8[4] = b.x; in8[5] = b.y; in8[6] = b.z; in8[7] = b.w;
                } else {
#pragma unroll
                    for (int c = 0; c < 8; c++) in8[c] = 0.f;
                }
                int tap = (dz * 3 + dy) * 3 + dx;
                const float* wp = &sw[tap];
#pragma unroll
                for (int oc = 0; oc < 18; oc++) {
#pragma unroll
                    for (int ci = 0; ci < 8; ci++)
                        acc[oc] = fmaf(in8[ci], wp[(oc * 8 + ci) * 27], acc[oc]);
                }
            }
        }
    }

#pragma unroll
    for (int j = 0; j < 18; j++) g_off[j * V + v] = acc[j];

    // warp-level BN partial sums -> global atomics
    int lane = tid & 31;
#pragma unroll
    for (int j = 0; j < 18; j++) {
        float s = acc[j];
        float q = acc[j] * acc[j];
#pragma unroll
        for (int o = 16; o; o >>= 1) {
            s += __shfl_down_sync(0xFFFFFFFFu, s, o);
            q += __shfl_down_sync(0xFFFFFFFFu, q, o);
        }
        if (lane == 0) {
            atomicAdd(&g_bnsum[j], s);
            atomicAdd(&g_bnsq[j], q);
        }
    }
}

// ---------------- kernel 3: finalize BN into folded scale/shift ----------------
__global__ void k_bn_final(const float* __restrict__ bng, const float* __restrict__ bnb) {
    int j = threadIdx.x;
    if (j < 18) {
        float mean = g_bnsum[j] * (1.0f / V);
        float var  = g_bnsq[j] * (1.0f / V) - mean * mean;
        float s = bng[j] * rsqrtf(var + EPSV);
        g_bns[j] = s;
        g_bnt[j] = bnb[j] - mean * s;
    }
}

// trilinear corner accumulate: 8 channels from transposed feat
__device__ __forceinline__ void corner_acc(float* dv, int zi, int yi, int xi, float wt) {
    const float4* p = reinterpret_cast<const float4*>(
        &g_ft[((((zi << 6) + yi) << 6) + xi) * 8]);
    float4 a = p[0], b = p[1];
    dv[0] = fmaf(a.x, wt, dv[0]);
    dv[1] = fmaf(a.y, wt, dv[1]);
    dv[2] = fmaf(a.z, wt, dv[2]);
    dv[3] = fmaf(a.w, wt, dv[3]);
    dv[4] = fmaf(b.x, wt, dv[4]);
    dv[5] = fmaf(b.y, wt, dv[5]);
    dv[6] = fmaf(b.z, wt, dv[6]);
    dv[7] = fmaf(b.w, wt, dv[7]);
}

// ---------------- kernel 4: BN+tanh, cumsum coords, trilinear, dcn conv, GN partial stats ----------------
__global__ void __launch_bounds__(256) k_main(const float* __restrict__ dcnw,
                                              const float* __restrict__ dcnb) {
    __shared__ float sw[16 * 8 * 9];   // 1152
    __shared__ float sb[16];
    int tid = threadIdx.x;
    for (int i = tid; i < 1152; i += 256) sw[i] = dcnw[i];
    if (tid < 16) sb[tid] = dcnb[tid];
    __syncthreads();

    int v = blockIdx.x * 256 + tid;
    int h = v & 63, w = (v >> 6) & 63, d = v >> 12;

    // BN + tanh for the 18 used offset channels
    float zo[9], yo[9];
#pragma unroll
    for (int j = 0; j < 9; j++)
        zo[j] = tanhf(fmaf(g_off[j * V + v], g_bns[j], g_bnt[j]));
#pragma unroll
    for (int j = 0; j < 9; j++)
        yo[j] = tanhf(fmaf(g_off[(9 + j) * V + v], g_bns[9 + j], g_bnt[9 + j]));

    // cumsum outward from center (k=4), matching reference accumulation order
#pragma unroll
    for (int k = 5; k < 9; k++) { zo[k] += zo[k - 1]; yo[k] += yo[k - 1]; }
#pragma unroll
    for (int k = 3; k >= 0; k--) { zo[k] += zo[k + 1]; yo[k] += yo[k + 1]; }

    float acc[16];
#pragma unroll
    for (int co = 0; co < 16; co++) acc[co] = sb[co];

#pragma unroll
    for (int k = 0; k < 9; k++) {
        float zf = (float)d + zo[k];
        float yf = (float)w + yo[k];
        int   xi = h + k - 4;
        float xf = (float)xi;

        int zb = (int)floorf(zf);
        int yb = (int)floorf(yf);
        int z0 = min(max(zb, 0), 63),     z1 = min(max(zb + 1, 0), 63);
        int y0 = min(max(yb, 0), 63),     y1 = min(max(yb + 1, 0), 63);
        int x0 = min(max(xi, 0), 63),     x1 = min(max(xi + 1, 0), 63);

        float wz0 = (float)z1 - zf, wz1 = zf - (float)z0;
        float wy0 = (float)y1 - yf, wy1 = yf - (float)y0;
        float wx0 = (float)x1 - xf, wx1 = xf - (float)x0;

        float dv[8];
#pragma unroll
        for (int c = 0; c < 8; c++) dv[c] = 0.f;

        float wz0y0 = wz0 * wy0, wz0y1 = wz0 * wy1;
        float wz1y0 = wz1 * wy0, wz1y1 = wz1 * wy1;
        corner_acc(dv, z0, y0, x0, wz0y0 * wx0);
        corner_acc(dv, z0, y0, x1, wz0y0 * wx1);
        corner_acc(dv, z0, y1, x0, wz0y1 * wx0);
        corner_acc(dv, z0, y1, x1, wz0y1 * wx1);
        corner_acc(dv, z1, y0, x0, wz1y0 * wx0);
        corner_acc(dv, z1, y0, x1, wz1y0 * wx1);
        corner_acc(dv, z1, y1, x0, wz1y1 * wx0);
        corner_acc(dv, z1, y1, x1, wz1y1 * wx1);

#pragma unroll
        for (int co = 0; co < 16; co++) {
#pragma unroll
            for (int ci = 0; ci < 8; ci++)
                acc[co] = fmaf(dv[ci], sw[co * 72 + ci * 9 + k], acc[co]);
        }
    }

#pragma unroll
    for (int co = 0; co < 16; co++) g_conv[co * V + v] = acc[co];

    // GN partial stats (4 groups of 4 channels)
    int lane = tid & 31;
#pragma unroll
    for (int g = 0; g < 4; g++) {
        float s = acc[4 * g] + acc[4 * g + 1] + acc[4 * g + 2] + acc[4 * g + 3];
        float q = acc[4 * g] * acc[4 * g] + acc[4 * g + 1] * acc[4 * g + 1]
                + acc[4 * g + 2] * acc[4 * g + 2] + acc[4 * g + 3] * acc[4 * g + 3];
#pragma unroll
        for (int o = 16; o; o >>= 1) {
            s += __shfl_down_sync(0xFFFFFFFFu, s, o);
            q += __shfl_down_sync(0xFFFFFFFFu, q, o);
        }
        if (lane == 0) {
            atomicAdd(&g_gsum[g], s);
            atomicAdd(&g_gsq[g], q);
        }
    }
}

// ---------------- kernel 5: finalize GN into per-channel scale/shift ----------------
__global__ void k_gn_final(const float* __restrict__ gng, const float* __restrict__ gnb) {
    int co = threadIdx.x;
    if (co < 16) {
        int g = co >> 2;
        float inv = 1.0f / (4.0f * (float)V);
        float mean = g_gsum[g] * inv;
        float var  = g_gsq[g] * inv - mean * mean;
        float s = gng[co] * rsqrtf(var + EPSV);
        g_gns[co] = s;
        g_gnt[co] = gnb[co] - mean * s;
    }
}

// ---------------- kernel 6: apply GN + ReLU ----------------
__global__ void k_gn_apply(float* __restrict__ out) {
    int i = blockIdx.x * 256 + threadIdx.x;   // 16*V total
    int co = i >> 18;                          // V = 2^18
    float val = fmaf(g_conv[i], g_gns[co], g_gnt[co]);
    out[i] = fmaxf(val, 0.f);
}

// ---------------- launch ----------------
extern "C" void kernel_launch(void* const* d_in, const int* in_sizes, int n_in,
                              void* d_out, int out_size) {
    (void)in_sizes; (void)n_in; (void)out_size;
    const float* f    = (const float*)d_in[0];
    const float* offw = (const float*)d_in[1];
    const float* offb = (const float*)d_in[2];
    const float* bng  = (const float*)d_in[3];
    const float* bnb  = (const float*)d_in[4];
    const float* dcnw = (const float*)d_in[5];
    const float* dcnb = (const float*)d_in[6];
    const float* gng  = (const float*)d_in[7];
    const float* gnb  = (const float*)d_in[8];
    float* out = (float*)d_out;

    k_transpose<<<1024, 256>>>(f);
    k_conv_off<<<1024, 256>>>(offw, offb);
    k_bn_final<<<1, 32>>>(bng, bnb);
    k_main<<<1024, 256>>>(dcnw, dcnb);
    k_gn_final<<<1, 32>>>(gng, gnb);
    k_gn_apply<<<16384, 256>>>(out);
}

// round 2
// speedup vs baseline: 2.9642x; 2.9642x over previous
#include <cuda_runtime.h>
#include <math.h>

// Problem constants (fixed by setup_inputs)
#define V   262144          // 64*64*64
#define EPSV 1e-5f

// ---------------- scratch (__device__ globals; no allocation) ----------------
__device__ float g_ft[V * 8];        // f transposed to [D][W][H][C]  (8 MB)
__device__ float g_off[18 * V];      // offset conv output, [ch][voxel] (18 MB)
__device__ float g_conv[16 * V];     // dcn conv output pre-GN, [co][voxel] (16 MB)
__device__ float g_bnsum[18];
__device__ float g_bnsq[18];
__device__ float g_bns[18];          // folded BN scale
__device__ float g_bnt[18];          // folded BN shift
__device__ float g_gsum[4];
__device__ float g_gsq[4];
__device__ float g_gns[16];          // folded GN scale per out channel
__device__ float g_gnt[16];          // folded GN shift per out channel

// ---------------- kernel 1: transpose f [8][V] -> [V][8], zero stats ----------------
__global__ void k_transpose(const float* __restrict__ f) {
    int tid = threadIdx.x;
    if (blockIdx.x == 0 && tid < 22) {
        if (tid < 18) { g_bnsum[tid] = 0.f; g_bnsq[tid] = 0.f; }
        else          { g_gsum[tid - 18] = 0.f; g_gsq[tid - 18] = 0.f; }
    }
    int v = blockIdx.x * blockDim.x + tid;
    if (v >= V) return;
    float4 a, b;
    a.x = f[0 * V + v]; a.y = f[1 * V + v]; a.z = f[2 * V + v]; a.w = f[3 * V + v];
    b.x = f[4 * V + v]; b.y = f[5 * V + v]; b.z = f[6 * V + v]; b.w = f[7 * V + v];
    float4* dst = reinterpret_cast<float4*>(g_ft);
    dst[v * 2 + 0] = a;
    dst[v * 2 + 1] = b;
}

// ---------------- kernel 2: offset conv3d (18 out ch, 3x3x3, pad 1) + BN partial stats ----------------
__global__ void __launch_bounds__(256, 1)
k_conv_off(const float* __restrict__ offw, const float* __restrict__ offb) {
    __shared__ float sw[18 * 8 * 27];   // 3888 floats
    int tid = threadIdx.x;
    for (int i = tid; i < 3888; i += 256) sw[i] = offw[i];
    __syncthreads();

    int v = blockIdx.x * 256 + tid;
    int h = v & 63, w = (v >> 6) & 63, d = v >> 12;

    float acc[18];
#pragma unroll
    for (int j = 0; j < 18; j++) acc[j] = __ldg(&offb[j]);

#pragma unroll
    for (int dz = 0; dz < 3; dz++) {
        int zz = d + dz - 1;
#pragma unroll
        for (int dy = 0; dy < 3; dy++) {
            int yy = w + dy - 1;
#pragma unroll
            for (int dx = 0; dx < 3; dx++) {
                int xx = h + dx - 1;
                float in8[8];
                if ((unsigned)zz < 64u && (unsigned)yy < 64u && (unsigned)xx < 64u) {
                    const float4* p = reinterpret_cast<const float4*>(
                        &g_ft[((((zz << 6) + yy) << 6) + xx) * 8]);
                    float4 a = p[0], b = p[1];
                    in8[0] = a.x; in8[1] = a.y; in8[2] = a.z; in8[3] = a.w;
                    in8[4] = b.x; in8[5] = b.y; in8[6] = b.z; in8[7] = b.w;
                } else {
#pragma unroll
                    for (int c = 0; c < 8; c++) in8[c] = 0.f;
                }
                int tap = (dz * 3 + dy) * 3 + dx;
                const float* wp = &sw[tap];
#pragma unroll
                for (int oc = 0; oc < 18; oc++) {
#pragma unroll
                    for (int ci = 0; ci < 8; ci++)
                        acc[oc] = fmaf(in8[ci], wp[(oc * 8 + ci) * 27], acc[oc]);
                }
            }
        }
    }

#pragma unroll
    for (int j = 0; j < 18; j++) g_off[j * V + v] = acc[j];

    // warp-level BN partial sums -> global atomics
    int lane = tid & 31;
#pragma unroll
    for (int j = 0; j < 18; j++) {
        float s = acc[j];
        float q = acc[j] * acc[j];
#pragma unroll
        for (int o = 16; o; o >>= 1) {
            s += __shfl_down_sync(0xFFFFFFFFu, s, o);
            q += __shfl_down_sync(0xFFFFFFFFu, q, o);
        }
        if (lane == 0) {
            atomicAdd(&g_bnsum[j], s);
            atomicAdd(&g_bnsq[j], q);
        }
    }
}

// ---------------- kernel 3: finalize BN into folded scale/shift ----------------
__global__ void k_bn_final(const float* __restrict__ bng, const float* __restrict__ bnb) {
    int j = threadIdx.x;
    if (j < 18) {
        float mean = g_bnsum[j] * (1.0f / V);
        float var  = g_bnsq[j] * (1.0f / V) - mean * mean;
        float s = bng[j] * rsqrtf(var + EPSV);
        g_bns[j] = s;
        g_bnt[j] = bnb[j] - mean * s;
    }
}

// ---------------- kernel 4: BN+tanh, cumsum coords, trilinear, dcn conv, GN partial stats ----------------
__global__ void __launch_bounds__(256, 1)
k_main(const float* __restrict__ dcnw, const float* __restrict__ dcnb) {
    __shared__ float sw[16 * 8 * 9];   // 1152, layout [k][ci][co] below
    __shared__ float sb[16];
    int tid = threadIdx.x;
    // reorganize weights: sw2[k][ci][co] = dcnw[co*72 + ci*9 + k]
    for (int i = tid; i < 1152; i += 256) {
        int co = i / 72, r = i % 72, ci = r / 9, k = r % 9;
        sw[(k * 8 + ci) * 16 + co] = dcnw[i];
    }
    if (tid < 16) sb[tid] = dcnb[tid];
    __syncthreads();

    int v = blockIdx.x * 256 + tid;
    int h = v & 63, w = (v >> 6) & 63, d = v >> 12;

    // BN + tanh for the 18 used offset channels
    float zo[9], yo[9];
#pragma unroll
    for (int j = 0; j < 9; j++)
        zo[j] = tanhf(fmaf(g_off[j * V + v], g_bns[j], g_bnt[j]));
#pragma unroll
    for (int j = 0; j < 9; j++)
        yo[j] = tanhf(fmaf(g_off[(9 + j) * V + v], g_bns[9 + j], g_bnt[9 + j]));

    // cumsum outward from center (k=4), matching reference accumulation order
#pragma unroll
    for (int k = 5; k < 9; k++) { zo[k] += zo[k - 1]; yo[k] += yo[k - 1]; }
#pragma unroll
    for (int k = 3; k >= 0; k--) { zo[k] += zo[k + 1]; yo[k] += yo[k + 1]; }

    float acc[16];
#pragma unroll
    for (int co = 0; co < 16; co++) acc[co] = sb[co];

#pragma unroll
    for (int k = 0; k < 9; k++) {
        float zf = (float)d + zo[k];
        float yf = (float)w + yo[k];
        int   xi = h + k - 4;
        float xf = (float)xi;

        int zb = (int)floorf(zf);
        int yb = (int)floorf(yf);
        int z0 = min(max(zb, 0), 63),     z1 = min(max(zb + 1, 0), 63);
        int y0 = min(max(yb, 0), 63),     y1 = min(max(yb + 1, 0), 63);
        int x0 = min(max(xi, 0), 63),     x1 = min(max(xi + 1, 0), 63);

        float wz0 = (float)z1 - zf, wz1 = zf - (float)z0;
        float wy0 = (float)y1 - yf, wy1 = yf - (float)y0;
        float wx0 = (float)x1 - xf, wx1 = xf - (float)x0;

        // issue all 8 corner loads first (maximize MLP)
        const float4* base = reinterpret_cast<const float4*>(g_ft);
        int i000 = (((z0 << 6) + y0) << 6) + x0;
        int i001 = (((z0 << 6) + y0) << 6) + x1;
        int i010 = (((z0 << 6) + y1) << 6) + x0;
        int i011 = (((z0 << 6) + y1) << 6) + x1;
        int i100 = (((z1 << 6) + y0) << 6) + x0;
        int i101 = (((z1 << 6) + y0) << 6) + x1;
        int i110 = (((z1 << 6) + y1) << 6) + x0;
        int i111 = (((z1 << 6) + y1) << 6) + x1;
        float4 c000a = base[i000 * 2], c000b = base[i000 * 2 + 1];
        float4 c001a = base[i001 * 2], c001b = base[i001 * 2 + 1];
        float4 c010a = base[i010 * 2], c010b = base[i010 * 2 + 1];
        float4 c011a = base[i011 * 2], c011b = base[i011 * 2 + 1];
        float4 c100a = base[i100 * 2], c100b = base[i100 * 2 + 1];
        float4 c101a = base[i101 * 2], c101b = base[i101 * 2 + 1];
        float4 c110a = base[i110 * 2], c110b = base[i110 * 2 + 1];
        float4 c111a = base[i111 * 2], c111b = base[i111 * 2 + 1];

        float w000 = wz0 * wy0 * wx0, w001 = wz0 * wy0 * wx1;
        float w010 = wz0 * wy1 * wx0, w011 = wz0 * wy1 * wx1;
        float w100 = wz1 * wy0 * wx0, w101 = wz1 * wy0 * wx1;
        float w110 = wz1 * wy1 * wx0, w111 = wz1 * wy1 * wx1;

        float dv[8];
        dv[0] = c000a.x*w000 + c001a.x*w001 + c010a.x*w010 + c011a.x*w011
              + c100a.x*w100 + c101a.x*w101 + c110a.x*w110 + c111a.x*w111;
        dv[1] = c000a.y*w000 + c001a.y*w001 + c010a.y*w010 + c011a.y*w011
              + c100a.y*w100 + c101a.y*w101 + c110a.y*w110 + c111a.y*w111;
        dv[2] = c000a.z*w000 + c001a.z*w001 + c010a.z*w010 + c011a.z*w011
              + c100a.z*w100 + c101a.z*w101 + c110a.z*w110 + c111a.z*w111;
        dv[3] = c000a.w*w000 + c001a.w*w001 + c010a.w*w010 + c011a.w*w011
              + c100a.w*w100 + c101a.w*w101 + c110a.w*w110 + c111a.w*w111;
        dv[4] = c000b.x*w000 + c001b.x*w001 + c010b.x*w010 + c011b.x*w011
              + c100b.x*w100 + c101b.x*w101 + c110b.x*w110 + c111b.x*w111;
        dv[5] = c000b.y*w000 + c001b.y*w001 + c010b.y*w010 + c011b.y*w011
              + c100b.y*w100 + c101b.y*w101 + c110b.y*w110 + c111b.y*w111;
        dv[6] = c000b.z*w000 + c001b.z*w001 + c010b.z*w010 + c011b.z*w011
              + c100b.z*w100 + c101b.z*w101 + c110b.z*w110 + c111b.z*w111;
        dv[7] = c000b.w*w000 + c001b.w*w001 + c010b.w*w010 + c011b.w*w011
              + c100b.w*w100 + c101b.w*w101 + c110b.w*w110 + c111b.w*w111;

        const float* wp = &sw[(k * 8) * 16];
#pragma unroll
        for (int ci = 0; ci < 8; ci++) {
#pragma unroll
            for (int co = 0; co < 16; co++)
                acc[co] = fmaf(dv[ci], wp[ci * 16 + co], acc[co]);
        }
    }

#pragma unroll
    for (int co = 0; co < 16; co++) g_conv[co * V + v] = acc[co];

    // GN partial stats (4 groups of 4 channels)
    int lane = tid & 31;
#pragma unroll
    for (int g = 0; g < 4; g++) {
        float s = acc[4 * g] + acc[4 * g + 1] + acc[4 * g + 2] + acc[4 * g + 3];
        float q = acc[4 * g] * acc[4 * g] + acc[4 * g + 1] * acc[4 * g + 1]
                + acc[4 * g + 2] * acc[4 * g + 2] + acc[4 * g + 3] * acc[4 * g + 3];
#pragma unroll
        for (int o = 16; o; o >>= 1) {
            s += __shfl_down_sync(0xFFFFFFFFu, s, o);
            q += __shfl_down_sync(0xFFFFFFFFu, q, o);
        }
        if (lane == 0) {
            atomicAdd(&g_gsum[g], s);
            atomicAdd(&g_gsq[g], q);
        }
    }
}

// ---------------- kernel 5: finalize GN into per-channel scale/shift ----------------
__global__ void k_gn_final(const float* __restrict__ gng, const float* __restrict__ gnb) {
    int co = threadIdx.x;
    if (co < 16) {
        int g = co >> 2;
        float inv = 1.0f / (4.0f * (float)V);
        float mean = g_gsum[g] * inv;
        float var  = g_gsq[g] * inv - mean * mean;
        float s = gng[co] * rsqrtf(var + EPSV);
        g_gns[co] = s;
        g_gnt[co] = gnb[co] - mean * s;
    }
}

// ---------------- kernel 6: apply GN + ReLU ----------------
__global__ void k_gn_apply(float* __restrict__ out) {
    int i = blockIdx.x * 256 + threadIdx.x;   // 16*V total
    int co = i >> 18;                          // V = 2^18
    float val = fmaf(g_conv[i], g_gns[co], g_gnt[co]);
    out[i] = fmaxf(val, 0.f);
}

// ---------------- launch ----------------
extern "C" void kernel_launch(void* const* d_in, const int* in_sizes, int n_in,
                              void* d_out, int out_size) {
    (void)in_sizes; (void)n_in; (void)out_size;
    const float* f    = (const float*)d_in[0];
    const float* offw = (const float*)d_in[1];
    const float* offb = (const float*)d_in[2];
    const float* bng  = (const float*)d_in[3];
    const float* bnb  = (const float*)d_in[4];
    const float* dcnw = (const float*)d_in[5];
    const float* dcnb = (const float*)d_in[6];
    const float* gng  = (const float*)d_in[7];
    const float* gnb  = (const float*)d_in[8];
    float* out = (float*)d_out;

    k_transpose<<<1024, 256>>>(f);
    k_conv_off<<<1024, 256>>>(offw, offb);
    k_bn_final<<<1, 32>>>(bng, bnb);
    k_main<<<1024, 256>>>(dcnw, dcnb);
    k_gn_final<<<1, 32>>>(gng, gnb);
    k_gn_apply<<<16384, 256>>>(out);
}

// round 3
// speedup vs baseline: 3.3337x; 1.1247x over previous
#include <cuda_runtime.h>
#include <math.h>

#define V   262144          // 64*64*64
#define EPSV 1e-5f

// ---------------- scratch (__device__ globals; no allocation) ----------------
__device__ float g_ft[V * 8];        // f transposed to [D][W][H][C]  (8 MB)
__device__ float g_off[18 * V];      // offset conv output, [ch][voxel]
__device__ float g_conv[16 * V];     // dcn conv output pre-GN, [co][voxel]
__device__ float g_bnsum[18];
__device__ float g_bnsq[18];
__device__ float g_bns[18];
__device__ float g_bnt[18];
__device__ float g_gsum[4];
__device__ float g_gsq[4];
__device__ float g_gns[16];
__device__ float g_gnt[16];

// ---------------- kernel 1: transpose f [8][V] -> [V][8], zero stats ----------------
__global__ void k_transpose(const float* __restrict__ f) {
    int tid = threadIdx.x;
    if (blockIdx.x == 0 && tid < 22) {
        if (tid < 18) { g_bnsum[tid] = 0.f; g_bnsq[tid] = 0.f; }
        else          { g_gsum[tid - 18] = 0.f; g_gsq[tid - 18] = 0.f; }
    }
    int v = blockIdx.x * blockDim.x + tid;
    if (v >= V) return;
    float4 a, b;
    a.x = f[0 * V + v]; a.y = f[1 * V + v]; a.z = f[2 * V + v]; a.w = f[3 * V + v];
    b.x = f[4 * V + v]; b.y = f[5 * V + v]; b.z = f[6 * V + v]; b.w = f[7 * V + v];
    float4* dst = reinterpret_cast<float4*>(g_ft);
    dst[v * 2 + 0] = a;
    dst[v * 2 + 1] = b;
}

// ---------------- kernel 2: offset conv3d (18 out ch, 3x3x3, pad 1) + BN stats ----------------
// Weights staged to smem in [tap][oc][ci] layout so the 8 ci weights for each
// (tap, oc) are contiguous -> LDS.128 pairs instead of scalar LDS per FMA.
__global__ void __launch_bounds__(256, 1)
k_conv_off(const float* __restrict__ offw, const float* __restrict__ offb) {
    __shared__ float sw[27 * 18 * 8];   // 3888 floats, [tap][oc][ci]
    int tid = threadIdx.x;
    for (int i = tid; i < 3888; i += 256) {
        int oc = i / 216, r = i % 216, ci = r / 27, tap = r % 27;   // source index
        sw[(tap * 18 + oc) * 8 + ci] = offw[i];
    }
    __syncthreads();

    int v = blockIdx.x * 256 + tid;
    int h = v & 63, w = (v >> 6) & 63, d = v >> 12;

    float acc[18];
#pragma unroll
    for (int j = 0; j < 18; j++) acc[j] = __ldg(&offb[j]);

#pragma unroll
    for (int dz = 0; dz < 3; dz++) {
        int zz = d + dz - 1;
#pragma unroll
        for (int dy = 0; dy < 3; dy++) {
            int yy = w + dy - 1;
#pragma unroll
            for (int dx = 0; dx < 3; dx++) {
                int xx = h + dx - 1;
                float4 a, b;
                if ((unsigned)zz < 64u && (unsigned)yy < 64u && (unsigned)xx < 64u) {
                    const float4* p = reinterpret_cast<const float4*>(
                        &g_ft[((((zz << 6) + yy) << 6) + xx) * 8]);
                    a = p[0]; b = p[1];
                } else {
                    a = make_float4(0.f, 0.f, 0.f, 0.f);
                    b = a;
                }
                int tap = (dz * 3 + dy) * 3 + dx;
                const float4* wp = reinterpret_cast<const float4*>(&sw[tap * 144]);
#pragma unroll
                for (int oc = 0; oc < 18; oc++) {
                    float4 w0 = wp[oc * 2];
                    float4 w1 = wp[oc * 2 + 1];
                    float s = acc[oc];
                    s = fmaf(a.x, w0.x, s);
                    s = fmaf(a.y, w0.y, s);
                    s = fmaf(a.z, w0.z, s);
                    s = fmaf(a.w, w0.w, s);
                    s = fmaf(b.x, w1.x, s);
                    s = fmaf(b.y, w1.y, s);
                    s = fmaf(b.z, w1.z, s);
                    s = fmaf(b.w, w1.w, s);
                    acc[oc] = s;
                }
            }
        }
    }

#pragma unroll
    for (int j = 0; j < 18; j++) g_off[j * V + v] = acc[j];

    int lane = tid & 31;
#pragma unroll
    for (int j = 0; j < 18; j++) {
        float s = acc[j];
        float q = acc[j] * acc[j];
#pragma unroll
        for (int o = 16; o; o >>= 1) {
            s += __shfl_down_sync(0xFFFFFFFFu, s, o);
            q += __shfl_down_sync(0xFFFFFFFFu, q, o);
        }
        if (lane == 0) {
            atomicAdd(&g_bnsum[j], s);
            atomicAdd(&g_bnsq[j], q);
        }
    }
}

// ---------------- kernel 3: finalize BN ----------------
__global__ void k_bn_final(const float* __restrict__ bng, const float* __restrict__ bnb) {
    int j = threadIdx.x;
    if (j < 18) {
        float mean = g_bnsum[j] * (1.0f / V);
        float var  = g_bnsq[j] * (1.0f / V) - mean * mean;
        float s = bng[j] * rsqrtf(var + EPSV);
        g_bns[j] = s;
        g_bnt[j] = bnb[j] - mean * s;
    }
}

// ---------------- kernel 4: BN+tanh, cumsum, trilinear, dcn conv, GN stats ----------------
__global__ void __launch_bounds__(256, 2)
k_main(const float* __restrict__ dcnw, const float* __restrict__ dcnb) {
    __shared__ float sw[16 * 8 * 9];   // layout [k][ci][co]
    __shared__ float sb[16];
    int tid = threadIdx.x;
    for (int i = tid; i < 1152; i += 256) {
        int co = i / 72, r = i % 72, ci = r / 9, k = r % 9;
        sw[(k * 8 + ci) * 16 + co] = dcnw[i];
    }
    if (tid < 16) sb[tid] = dcnb[tid];
    __syncthreads();

    int v = blockIdx.x * 256 + tid;
    int h = v & 63, w = (v >> 6) & 63, d = v >> 12;

    float zo[9], yo[9];
#pragma unroll
    for (int j = 0; j < 9; j++)
        zo[j] = tanhf(fmaf(g_off[j * V + v], g_bns[j], g_bnt[j]));
#pragma unroll
    for (int j = 0; j < 9; j++)
        yo[j] = tanhf(fmaf(g_off[(9 + j) * V + v], g_bns[9 + j], g_bnt[9 + j]));

#pragma unroll
    for (int k = 5; k < 9; k++) { zo[k] += zo[k - 1]; yo[k] += yo[k - 1]; }
#pragma unroll
    for (int k = 3; k >= 0; k--) { zo[k] += zo[k + 1]; yo[k] += yo[k + 1]; }

    float acc[16];
#pragma unroll
    for (int co = 0; co < 16; co++) acc[co] = sb[co];

#pragma unroll
    for (int k = 0; k < 9; k++) {
        float zf = (float)d + zo[k];
        float yf = (float)w + yo[k];
        int   xi = h + k - 4;
        float xf = (float)xi;

        int zb = (int)floorf(zf);
        int yb = (int)floorf(yf);
        int z0 = min(max(zb, 0), 63),     z1 = min(max(zb + 1, 0), 63);
        int y0 = min(max(yb, 0), 63),     y1 = min(max(yb + 1, 0), 63);
        int x0 = min(max(xi, 0), 63),     x1 = min(max(xi + 1, 0), 63);

        float wz0 = (float)z1 - zf, wz1 = zf - (float)z0;
        float wy0 = (float)y1 - yf, wy1 = yf - (float)y0;
        float wx0 = (float)x1 - xf, wx1 = xf - (float)x0;

        float w00 = wy0 * wx0, w01 = wy0 * wx1, w10 = wy1 * wx0, w11 = wy1 * wx1;

        const float4* base = reinterpret_cast<const float4*>(g_ft);
        float dv[8];

        // ---- z0 plane: 4 corners, 8 LDG.128 in flight ----
        {
            int iA = ((((z0 << 6) + y0) << 6) + x0) * 2;
            int iB = ((((z0 << 6) + y0) << 6) + x1) * 2;
            int iC = ((((z0 << 6) + y1) << 6) + x0) * 2;
            int iD = ((((z0 << 6) + y1) << 6) + x1) * 2;
            float4 Aa = base[iA], Ab = base[iA + 1];
            float4 Ba = base[iB], Bb = base[iB + 1];
            float4 Ca = base[iC], Cb = base[iC + 1];
            float4 Da = base[iD], Db = base[iD + 1];
            float a00 = wz0 * w00, a01 = wz0 * w01, a10 = wz0 * w10, a11 = wz0 * w11;
            dv[0] = Aa.x*a00 + Ba.x*a01 + Ca.x*a10 + Da.x*a11;
            dv[1] = Aa.y*a00 + Ba.y*a01 + Ca.y*a10 + Da.y*a11;
            dv[2] = Aa.z*a00 + Ba.z*a01 + Ca.z*a10 + Da.z*a11;
            dv[3] = Aa.w*a00 + Ba.w*a01 + Ca.w*a10 + Da.w*a11;
            dv[4] = Ab.x*a00 + Bb.x*a01 + Cb.x*a10 + Db.x*a11;
            dv[5] = Ab.y*a00 + Bb.y*a01 + Cb.y*a10 + Db.y*a11;
            dv[6] = Ab.z*a00 + Bb.z*a01 + Cb.z*a10 + Db.z*a11;
            dv[7] = Ab.w*a00 + Bb.w*a01 + Cb.w*a10 + Db.w*a11;
        }
        // ---- z1 plane ----
        {
            int iA = ((((z1 << 6) + y0) << 6) + x0) * 2;
            int iB = ((((z1 << 6) + y0) << 6) + x1) * 2;
            int iC = ((((z1 << 6) + y1) << 6) + x0) * 2;
            int iD = ((((z1 << 6) + y1) << 6) + x1) * 2;
            float4 Aa = base[iA], Ab = base[iA + 1];
            float4 Ba = base[iB], Bb = base[iB + 1];
            float4 Ca = base[iC], Cb = base[iC + 1];
            float4 Da = base[iD], Db = base[iD + 1];
            float a00 = wz1 * w00, a01 = wz1 * w01, a10 = wz1 * w10, a11 = wz1 * w11;
            dv[0] += Aa.x*a00 + Ba.x*a01 + Ca.x*a10 + Da.x*a11;
            dv[1] += Aa.y*a00 + Ba.y*a01 + Ca.y*a10 + Da.y*a11;
            dv[2] += Aa.z*a00 + Ba.z*a01 + Ca.z*a10 + Da.z*a11;
            dv[3] += Aa.w*a00 + Ba.w*a01 + Ca.w*a10 + Da.w*a11;
            dv[4] += Ab.x*a00 + Bb.x*a01 + Cb.x*a10 + Db.x*a11;
            dv[5] += Ab.y*a00 + Bb.y*a01 + Cb.y*a10 + Db.y*a11;
            dv[6] += Ab.z*a00 + Bb.z*a01 + Cb.z*a10 + Db.z*a11;
            dv[7] += Ab.w*a00 + Bb.w*a01 + Cb.w*a10 + Db.w*a11;
        }

        const float* wp = &sw[(k * 8) * 16];
#pragma unroll
        for (int ci = 0; ci < 8; ci++) {
#pragma unroll
            for (int co = 0; co < 16; co++)
                acc[co] = fmaf(dv[ci], wp[ci * 16 + co], acc[co]);
        }
    }

#pragma unroll
    for (int co = 0; co < 16; co++) g_conv[co * V + v] = acc[co];

    int lane = tid & 31;
#pragma unroll
    for (int g = 0; g < 4; g++) {
        float s = acc[4 * g] + acc[4 * g + 1] + acc[4 * g + 2] + acc[4 * g + 3];
        float q = acc[4 * g] * acc[4 * g] + acc[4 * g + 1] * acc[4 * g + 1]
                + acc[4 * g + 2] * acc[4 * g + 2] + acc[4 * g + 3] * acc[4 * g + 3];
#pragma unroll
        for (int o = 16; o; o >>= 1) {
            s += __shfl_down_sync(0xFFFFFFFFu, s, o);
            q += __shfl_down_sync(0xFFFFFFFFu, q, o);
        }
        if (lane == 0) {
            atomicAdd(&g_gsum[g], s);
            atomicAdd(&g_gsq[g], q);
        }
    }
}

// ---------------- kernel 5: finalize GN ----------------
__global__ void k_gn_final(const float* __restrict__ gng, const float* __restrict__ gnb) {
    int co = threadIdx.x;
    if (co < 16) {
        int g = co >> 2;
        float inv = 1.0f / (4.0f * (float)V);
        float mean = g_gsum[g] * inv;
        float var  = g_gsq[g] * inv - mean * mean;
        float s = gng[co] * rsqrtf(var + EPSV);
        g_gns[co] = s;
        g_gnt[co] = gnb[co] - mean * s;
    }
}

// ---------------- kernel 6: apply GN + ReLU (vectorized) ----------------
__global__ void k_gn_apply(float* __restrict__ out) {
    int i4 = blockIdx.x * 256 + threadIdx.x;   // over 16*V/4 float4s
    int i  = i4 * 4;
    int co = i >> 18;                           // V = 2^18; 4 elems share channel
    float s = g_gns[co], t = g_gnt[co];
    const float4* src = reinterpret_cast<const float4*>(g_conv);
    float4 a = src[i4];
    float4 r;
    r.x = fmaxf(fmaf(a.x, s, t), 0.f);
    r.y = fmaxf(fmaf(a.y, s, t), 0.f);
    r.z = fmaxf(fmaf(a.z, s, t), 0.f);
    r.w = fmaxf(fmaf(a.w, s, t), 0.f);
    reinterpret_cast<float4*>(out)[i4] = r;
}

// ---------------- launch ----------------
extern "C" void kernel_launch(void* const* d_in, const int* in_sizes, int n_in,
                              void* d_out, int out_size) {
    (void)in_sizes; (void)n_in; (void)out_size;
    const float* f    = (const float*)d_in[0];
    const float* offw = (const float*)d_in[1];
    const float* offb = (const float*)d_in[2];
    const float* bng  = (const float*)d_in[3];
    const float* bnb  = (const float*)d_in[4];
    const float* dcnw = (const float*)d_in[5];
    const float* dcnb = (const float*)d_in[6];
    const float* gng  = (const float*)d_in[7];
    const float* gnb  = (const float*)d_in[8];
    float* out = (float*)d_out;

    k_transpose<<<1024, 256>>>(f);
    k_conv_off<<<1024, 256>>>(offw, offb);
    k_bn_final<<<1, 32>>>(bng, bnb);
    k_main<<<1024, 256>>>(dcnw, dcnb);
    k_gn_final<<<1, 32>>>(gng, gnb);
    k_gn_apply<<<4096, 256>>>(out);
}

// round 4
// speedup vs baseline: 3.4138x; 1.0240x over previous
#include <cuda_runtime.h>
#include <math.h>

#define V    262144         // 64^3
#define PD   66             // padded dim
#define PS   (PD*PD)        // 4356
#define PV   (PD*PD*PD)     // 287496
#define PBASE (PS + PD + 1) // 4423 : offset of voxel (0,0,0) in padded volume
#define EPSV 1e-5f

// ---------------- scratch (__device__ globals; no allocation) ----------------
__device__ float g_ft[PV * 8];       // zero-padded transposed feat [66][66][66][8] (9.2 MB)
__device__ float g_off[18 * V];
__device__ float g_conv[16 * V];
__device__ float g_bnsum[18];
__device__ float g_bnsq[18];
__device__ float g_bns[18];
__device__ float g_bnt[18];
__device__ float g_gsum[4];
__device__ float g_gsq[4];
__device__ float g_gns[16];
__device__ float g_gnt[16];

// ---------------- kernel 1: pad+transpose f [8][V] -> [66^3][8], zero halo & stats ----------------
__global__ void k_transpose(const float* __restrict__ f) {
    int tid = threadIdx.x;
    if (blockIdx.x == 0 && tid < 22) {
        if (tid < 18) { g_bnsum[tid] = 0.f; g_bnsq[tid] = 0.f; }
        else          { g_gsum[tid - 18] = 0.f; g_gsq[tid - 18] = 0.f; }
    }
    int pv = blockIdx.x * blockDim.x + tid;
    if (pv >= PV) return;
    int z = pv / PS, r = pv % PS, y = r / PD, x = r % PD;
    float4 a = make_float4(0.f, 0.f, 0.f, 0.f), b = a;
    if (z >= 1 && z <= 64 && y >= 1 && y <= 64 && x >= 1 && x <= 64) {
        int v = (((z - 1) << 6) + (y - 1) << 6) + (x - 1);
        a.x = f[0 * V + v]; a.y = f[1 * V + v]; a.z = f[2 * V + v]; a.w = f[3 * V + v];
        b.x = f[4 * V + v]; b.y = f[5 * V + v]; b.z = f[6 * V + v]; b.w = f[7 * V + v];
    }
    float4* dst = reinterpret_cast<float4*>(g_ft);
    dst[pv * 2 + 0] = a;
    dst[pv * 2 + 1] = b;
}

// ---------------- kernel 2: offset conv3d (18 ch, 3x3x3) branch-free, rolled tap loop ----------------
__global__ void __launch_bounds__(256, 2)
k_conv_off(const float* __restrict__ offw, const float* __restrict__ offb) {
    __shared__ float sw[27 * 18 * 8];   // [tap][oc][ci]
    __shared__ int   stoff[27];         // padded-volume float4 offsets per tap
    __shared__ float sbias[18];
    int tid = threadIdx.x;
    for (int i = tid; i < 3888; i += 256) {
        int oc = i / 216, r = i % 216, ci = r / 27, tap = r % 27;
        sw[(tap * 18 + oc) * 8 + ci] = offw[i];
    }
    if (tid < 27) {
        int dz = tid / 9 - 1, dy = (tid / 3) % 3 - 1, dx = tid % 3 - 1;
        stoff[tid] = (dz * PS + dy * PD + dx) * 2;     // in float4 units
    }
    if (tid < 18) sbias[tid] = offb[tid];
    __syncthreads();

    int v = blockIdx.x * 256 + tid;
    int h = v & 63, w = (v >> 6) & 63, d = v >> 12;
    int pc = (d * PS + w * PD + h + PBASE) * 2;        // center, float4 units

    float acc[18];
#pragma unroll
    for (int j = 0; j < 18; j++) acc[j] = sbias[j];

    const float4* base = reinterpret_cast<const float4*>(g_ft);
#pragma unroll 1
    for (int tap = 0; tap < 27; tap++) {
        int i4 = pc + stoff[tap];
        float4 a = base[i4], b = base[i4 + 1];
        const float4* wp = reinterpret_cast<const float4*>(&sw[tap * 144]);
#pragma unroll
        for (int oc = 0; oc < 18; oc++) {
            float4 w0 = wp[oc * 2];
            float4 w1 = wp[oc * 2 + 1];
            float s = acc[oc];
            s = fmaf(a.x, w0.x, s); s = fmaf(a.y, w0.y, s);
            s = fmaf(a.z, w0.z, s); s = fmaf(a.w, w0.w, s);
            s = fmaf(b.x, w1.x, s); s = fmaf(b.y, w1.y, s);
            s = fmaf(b.z, w1.z, s); s = fmaf(b.w, w1.w, s);
            acc[oc] = s;
        }
    }

#pragma unroll
    for (int j = 0; j < 18; j++) g_off[j * V + v] = acc[j];

    int lane = tid & 31;
#pragma unroll
    for (int j = 0; j < 18; j++) {
        float s = acc[j];
        float q = acc[j] * acc[j];
#pragma unroll
        for (int o = 16; o; o >>= 1) {
            s += __shfl_down_sync(0xFFFFFFFFu, s, o);
            q += __shfl_down_sync(0xFFFFFFFFu, q, o);
        }
        if (lane == 0) {
            atomicAdd(&g_bnsum[j], s);
            atomicAdd(&g_bnsq[j], q);
        }
    }
}

// ---------------- kernel 3: finalize BN ----------------
__global__ void k_bn_final(const float* __restrict__ bng, const float* __restrict__ bnb) {
    int j = threadIdx.x;
    if (j < 18) {
        float mean = g_bnsum[j] * (1.0f / V);
        float var  = g_bnsq[j] * (1.0f / V) - mean * mean;
        float s = bng[j] * rsqrtf(var + EPSV);
        g_bns[j] = s;
        g_bnt[j] = bnb[j] - mean * s;
    }
}

// ---------------- kernel 4: BN+tanh, cumsum, 4-corner trilinear, dcn conv, GN stats ----------------
// x is undeformed & integer: x-interp weights are exactly (1,0) for 0<=xi<=62,
// zero at xi==63, and OOB x contributions cancel exactly. -> 4 corners per tap.
__global__ void __launch_bounds__(256, 2)
k_main(const float* __restrict__ dcnw, const float* __restrict__ dcnb) {
    __shared__ float sw[16 * 8 * 9];   // [k][ci][co]
    __shared__ float sb[16];
    int tid = threadIdx.x;
    for (int i = tid; i < 1152; i += 256) {
        int co = i / 72, r = i % 72, ci = r / 9, k = r % 9;
        sw[(k * 8 + ci) * 16 + co] = dcnw[i];
    }
    if (tid < 16) sb[tid] = dcnb[tid];
    __syncthreads();

    int v = blockIdx.x * 256 + tid;
    int h = v & 63, w = (v >> 6) & 63, d = v >> 12;

    float zo[9], yo[9];
#pragma unroll
    for (int j = 0; j < 9; j++)
        zo[j] = tanhf(fmaf(g_off[j * V + v], g_bns[j], g_bnt[j]));
#pragma unroll
    for (int j = 0; j < 9; j++)
        yo[j] = tanhf(fmaf(g_off[(9 + j) * V + v], g_bns[9 + j], g_bnt[9 + j]));

#pragma unroll
    for (int k = 5; k < 9; k++) { zo[k] += zo[k - 1]; yo[k] += yo[k - 1]; }
#pragma unroll
    for (int k = 3; k >= 0; k--) { zo[k] += zo[k + 1]; yo[k] += yo[k + 1]; }

    float acc[16];
#pragma unroll
    for (int co = 0; co < 16; co++) acc[co] = sb[co];

    const float4* base = reinterpret_cast<const float4*>(g_ft);

#pragma unroll
    for (int k = 0; k < 9; k++) {
        float zf = (float)d + zo[k];
        float yf = (float)w + yo[k];
        int   xi = h + k - 4;
        float valid = ((unsigned)xi < 63u) ? 1.f : 0.f;
        int   xc = min(max(xi, 0), 63);

        int zb = (int)floorf(zf);
        int yb = (int)floorf(yf);
        int z0 = min(max(zb, 0), 63),  z1 = min(max(zb + 1, 0), 63);
        int y0 = min(max(yb, 0), 63),  y1 = min(max(yb + 1, 0), 63);

        float wz0 = (float)z1 - zf, wz1 = zf - (float)z0;
        float wy0 = (float)y1 - yf, wy1 = yf - (float)y0;

        float c00 = wz0 * wy0 * valid;
        float c01 = wz0 * wy1 * valid;
        float c10 = wz1 * wy0 * valid;
        float c11 = wz1 * wy1 * valid;

        int zr0 = z0 * PS, zr1 = z1 * PS;
        int yr0 = y0 * PD, yr1 = y1 * PD;
        int i00 = (zr0 + yr0 + xc + PBASE) * 2;
        int i01 = (zr0 + yr1 + xc + PBASE) * 2;
        int i10 = (zr1 + yr0 + xc + PBASE) * 2;
        int i11 = (zr1 + yr1 + xc + PBASE) * 2;

        float4 Aa = base[i00], Ab = base[i00 + 1];
        float4 Ba = base[i01], Bb = base[i01 + 1];
        float4 Ca = base[i10], Cb = base[i10 + 1];
        float4 Da = base[i11], Db = base[i11 + 1];

        float dv[8];
        dv[0] = Aa.x*c00 + Ba.x*c01 + Ca.x*c10 + Da.x*c11;
        dv[1] = Aa.y*c00 + Ba.y*c01 + Ca.y*c10 + Da.y*c11;
        dv[2] = Aa.z*c00 + Ba.z*c01 + Ca.z*c10 + Da.z*c11;
        dv[3] = Aa.w*c00 + Ba.w*c01 + Ca.w*c10 + Da.w*c11;
        dv[4] = Ab.x*c00 + Bb.x*c01 + Cb.x*c10 + Db.x*c11;
        dv[5] = Ab.y*c00 + Bb.y*c01 + Cb.y*c10 + Db.y*c11;
        dv[6] = Ab.z*c00 + Bb.z*c01 + Cb.z*c10 + Db.z*c11;
        dv[7] = Ab.w*c00 + Bb.w*c01 + Cb.w*c10 + Db.w*c11;

        const float* wp = &sw[(k * 8) * 16];
#pragma unroll
        for (int ci = 0; ci < 8; ci++) {
#pragma unroll
            for (int co = 0; co < 16; co++)
                acc[co] = fmaf(dv[ci], wp[ci * 16 + co], acc[co]);
        }
    }

#pragma unroll
    for (int co = 0; co < 16; co++) g_conv[co * V + v] = acc[co];

    int lane = tid & 31;
#pragma unroll
    for (int g = 0; g < 4; g++) {
        float s = acc[4 * g] + acc[4 * g + 1] + acc[4 * g + 2] + acc[4 * g + 3];
        float q = acc[4 * g] * acc[4 * g] + acc[4 * g + 1] * acc[4 * g + 1]
                + acc[4 * g + 2] * acc[4 * g + 2] + acc[4 * g + 3] * acc[4 * g + 3];
#pragma unroll
        for (int o = 16; o; o >>= 1) {
            s += __shfl_down_sync(0xFFFFFFFFu, s, o);
            q += __shfl_down_sync(0xFFFFFFFFu, q, o);
        }
        if (lane == 0) {
            atomicAdd(&g_gsum[g], s);
            atomicAdd(&g_gsq[g], q);
        }
    }
}

// ---------------- kernel 5: finalize GN ----------------
__global__ void k_gn_final(const float* __restrict__ gng, const float* __restrict__ gnb) {
    int co = threadIdx.x;
    if (co < 16) {
        int g = co >> 2;
        float inv = 1.0f / (4.0f * (float)V);
        float mean = g_gsum[g] * inv;
        float var  = g_gsq[g] * inv - mean * mean;
        float s = gng[co] * rsqrtf(var + EPSV);
        g_gns[co] = s;
        g_gnt[co] = gnb[co] - mean * s;
    }
}

// ---------------- kernel 6: apply GN + ReLU (vectorized) ----------------
__global__ void k_gn_apply(float* __restrict__ out) {
    int i4 = blockIdx.x * 256 + threadIdx.x;
    int co = (i4 * 4) >> 18;
    float s = g_gns[co], t = g_gnt[co];
    float4 a = reinterpret_cast<const float4*>(g_conv)[i4];
    float4 r;
    r.x = fmaxf(fmaf(a.x, s, t), 0.f);
    r.y = fmaxf(fmaf(a.y, s, t), 0.f);
    r.z = fmaxf(fmaf(a.z, s, t), 0.f);
    r.w = fmaxf(fmaf(a.w, s, t), 0.f);
    reinterpret_cast<float4*>(out)[i4] = r;
}

// ---------------- launch ----------------
extern "C" void kernel_launch(void* const* d_in, const int* in_sizes, int n_in,
                              void* d_out, int out_size) {
    (void)in_sizes; (void)n_in; (void)out_size;
    const float* f    = (const float*)d_in[0];
    const float* offw = (const float*)d_in[1];
    const float* offb = (const float*)d_in[2];
    const float* bng  = (const float*)d_in[3];
    const float* bnb  = (const float*)d_in[4];
    const float* dcnw = (const float*)d_in[5];
    const float* dcnb = (const float*)d_in[6];
    const float* gng  = (const float*)d_in[7];
    const float* gnb  = (const float*)d_in[8];
    float* out = (float*)d_out;

    k_transpose<<<(PV + 255) / 256, 256>>>(f);
    k_conv_off<<<1024, 256>>>(offw, offb);
    k_bn_final<<<1, 32>>>(bng, bnb);
    k_main<<<1024, 256>>>(dcnw, dcnb);
    k_gn_final<<<1, 32>>>(gng, gnb);
    k_gn_apply<<<4096, 256>>>(out);
}

// round 6
// speedup vs baseline: 4.3185x; 1.2650x over previous
#include <cuda_runtime.h>
#include <math.h>

#define V    262144         // 64^3
#define PD   66             // padded dim
#define PS   (PD*PD)        // 4356
#define PV   (PD*PD*PD)     // 287496
#define PBASE (PS + PD + 1) // offset of voxel (0,0,0) in padded volume
#define EPSV 1e-5f

// ---------------- scratch (__device__ globals; no allocation) ----------------
__device__ float g_ft[PV * 8];       // zero-padded transposed feat [66][66][66][8]
__device__ float g_off[18 * V];
__device__ float g_conv[16 * V];
__device__ float g_bnsum[18];
__device__ float g_bnsq[18];
__device__ float g_bns[18];
__device__ float g_bnt[18];
__device__ float g_gsum[4];
__device__ float g_gsq[4];
__device__ float g_gns[16];
__device__ float g_gnt[16];

// ---------------- kernel 1: pad+transpose f [8][V] -> [66^3][8], zero halo & stats ----------------
__global__ void k_transpose(const float* __restrict__ f) {
    int tid = threadIdx.x;
    if (blockIdx.x == 0 && tid < 22) {
        if (tid < 18) { g_bnsum[tid] = 0.f; g_bnsq[tid] = 0.f; }
        else          { g_gsum[tid - 18] = 0.f; g_gsq[tid - 18] = 0.f; }
    }
    int pv = blockIdx.x * blockDim.x + tid;
    if (pv >= PV) return;
    int z = pv / PS, r = pv % PS, y = r / PD, x = r % PD;
    float4 a = make_float4(0.f, 0.f, 0.f, 0.f), b = a;
    if (z >= 1 && z <= 64 && y >= 1 && y <= 64 && x >= 1 && x <= 64) {
        int v = (((z - 1) << 6) + (y - 1) << 6) + (x - 1);
        a.x = f[0 * V + v]; a.y = f[1 * V + v]; a.z = f[2 * V + v]; a.w = f[3 * V + v];
        b.x = f[4 * V + v]; b.y = f[5 * V + v]; b.z = f[6 * V + v]; b.w = f[7 * V + v];
    }
    float4* dst = reinterpret_cast<float4*>(g_ft);
    dst[pv * 2 + 0] = a;
    dst[pv * 2 + 1] = b;
}

// ---------------- kernel 2: offset conv3d, 4 voxels/thread, 2 passes of 9 oc ----------------
__global__ void __launch_bounds__(256, 2)
k_conv_off(const float* __restrict__ offw, const float* __restrict__ offb) {
    __shared__ float sw[27 * 18 * 8];   // [tap][oc][ci], tap = t9*3 + dx
    __shared__ int   srow[9];           // float4 offset of (dz,dy,-1) row start
    __shared__ float sbias[18];
    int tid = threadIdx.x;
    for (int i = tid; i < 3888; i += 256) {
        int oc = i / 216, r = i % 216, ci = r / 27, tap = r % 27;
        sw[(tap * 18 + oc) * 8 + ci] = offw[i];
    }
    if (tid < 9) {
        int dz = tid / 3 - 1, dy = tid % 3 - 1;
        srow[tid] = (dz * PS + dy * PD - 1) * 2;
    }
    if (tid < 18) sbias[tid] = offb[tid];
    __syncthreads();

    int t = blockIdx.x * 256 + tid;     // 65536 threads, 4 voxels each
    int h4 = (t & 15) << 2;
    int w  = (t >> 4) & 63;
    int d  = t >> 10;
    int pc = (d * PS + w * PD + h4 + PBASE) * 2;
    int v0 = t << 2;
    int lane = tid & 31;

    const float4* base = reinterpret_cast<const float4*>(g_ft);

#pragma unroll 1
    for (int ocb = 0; ocb < 18; ocb += 9) {
        float acc[9][4];
#pragma unroll
        for (int o = 0; o < 9; o++) {
            float b = sbias[ocb + o];
            acc[o][0] = b; acc[o][1] = b; acc[o][2] = b; acc[o][3] = b;
        }

#pragma unroll 1
        for (int t9 = 0; t9 < 9; t9++) {
            int rb = pc + srow[t9];
            float4 in[12];                        // 6 x-positions x 2 float4
#pragma unroll
            for (int j = 0; j < 12; j++) in[j] = base[rb + j];

            const float* swt = &sw[t9 * 432];     // 432 = 3*18*8
#pragma unroll
            for (int o = 0; o < 9; o++) {
#pragma unroll
                for (int dx = 0; dx < 3; dx++) {
                    const float4* wp = reinterpret_cast<const float4*>(
                        &swt[dx * 144 + (ocb + o) * 8]);
                    float4 w0 = wp[0], w1 = wp[1];
#pragma unroll
                    for (int vx = 0; vx < 4; vx++) {
                        float4 a  = in[2 * (vx + dx)];
                        float4 b2 = in[2 * (vx + dx) + 1];
                        float s = acc[o][vx];
                        s = fmaf(a.x,  w0.x, s); s = fmaf(a.y,  w0.y, s);
                        s = fmaf(a.z,  w0.z, s); s = fmaf(a.w,  w0.w, s);
                        s = fmaf(b2.x, w1.x, s); s = fmaf(b2.y, w1.y, s);
                        s = fmaf(b2.z, w1.z, s); s = fmaf(b2.w, w1.w, s);
                        acc[o][vx] = s;
                    }
                }
            }
        }

#pragma unroll
        for (int o = 0; o < 9; o++) {
            int j = ocb + o;
            float4 st = make_float4(acc[o][0], acc[o][1], acc[o][2], acc[o][3]);
            *reinterpret_cast<float4*>(&g_off[j * V + v0]) = st;
            float s = st.x + st.y + st.z + st.w;
            float q = st.x*st.x + st.y*st.y + st.z*st.z + st.w*st.w;
#pragma unroll
            for (int off = 16; off; off >>= 1) {
                s += __shfl_down_sync(0xFFFFFFFFu, s, off);
                q += __shfl_down_sync(0xFFFFFFFFu, q, off);
            }
            if (lane == 0) {
                atomicAdd(&g_bnsum[j], s);
                atomicAdd(&g_bnsq[j], q);
            }
        }
    }
}

// ---------------- kernel 3: finalize BN ----------------
__global__ void k_bn_final(const float* __restrict__ bng, const float* __restrict__ bnb) {
    int j = threadIdx.x;
    if (j < 18) {
        float mean = g_bnsum[j] * (1.0f / V);
        float var  = g_bnsq[j] * (1.0f / V) - mean * mean;
        float s = bng[j] * rsqrtf(var + EPSV);
        g_bns[j] = s;
        g_bnt[j] = bnb[j] - mean * s;
    }
}

// ---------------- kernel 4: pair-split main kernel ----------------
// Two threads per voxel: even lane handles channels 0-3, odd lane 4-7.
// Each corner gather is a single LDG.128 (pair-lanes share the cache line).
__global__ void __launch_bounds__(512, 1)
k_main(const float* __restrict__ dcnw, const float* __restrict__ dcnb) {
    __shared__ float sw[16 * 8 * 9];   // [k][ci][co]
    __shared__ float sb[16];
    int tid = threadIdx.x;
    for (int i = tid; i < 1152; i += 512) {
        int co = i / 72, r = i % 72, ci = r / 9, k = r % 9;
        sw[(k * 8 + ci) * 16 + co] = dcnw[i];
    }
    if (tid < 16) sb[tid] = dcnb[tid];
    __syncthreads();

    int t    = blockIdx.x * 512 + tid;
    int v    = t >> 1;
    int half = t & 1;
    int h = v & 63, w = (v >> 6) & 63, d = v >> 12;

    float zo[9], yo[9];
#pragma unroll
    for (int j = 0; j < 9; j++)
        zo[j] = tanhf(fmaf(g_off[j * V + v], g_bns[j], g_bnt[j]));
#pragma unroll
    for (int j = 0; j < 9; j++)
        yo[j] = tanhf(fmaf(g_off[(9 + j) * V + v], g_bns[9 + j], g_bnt[9 + j]));

#pragma unroll
    for (int k = 5; k < 9; k++) { zo[k] += zo[k - 1]; yo[k] += yo[k - 1]; }
#pragma unroll
    for (int k = 3; k >= 0; k--) { zo[k] += zo[k + 1]; yo[k] += yo[k + 1]; }

    float acc[16];
#pragma unroll
    for (int co = 0; co < 16; co++) acc[co] = half ? 0.f : sb[co];

    const float4* base = reinterpret_cast<const float4*>(g_ft);

#pragma unroll
    for (int k = 0; k < 9; k++) {
        float zf = (float)d + zo[k];
        float yf = (float)w + yo[k];
        int   xi = h + k - 4;
        float valid = ((unsigned)xi < 63u) ? 1.f : 0.f;
        int   xc = min(max(xi, 0), 63);

        int zb = (int)floorf(zf);
        int yb = (int)floorf(yf);
        int z0 = min(max(zb, 0), 63),  z1 = min(max(zb + 1, 0), 63);
        int y0 = min(max(yb, 0), 63),  y1 = min(max(yb + 1, 0), 63);

        float wz0 = (float)z1 - zf, wz1 = zf - (float)z0;
        float wy0 = (float)y1 - yf, wy1 = yf - (float)y0;

        float c00 = wz0 * wy0 * valid;
        float c01 = wz0 * wy1 * valid;
        float c10 = wz1 * wy0 * valid;
        float c11 = wz1 * wy1 * valid;

        int zr0 = z0 * PS, zr1 = z1 * PS;
        int yr0 = y0 * PD, yr1 = y1 * PD;
        int i00 = (zr0 + yr0 + xc + PBASE) * 2 + half;
        int i01 = (zr0 + yr1 + xc + PBASE) * 2 + half;
        int i10 = (zr1 + yr0 + xc + PBASE) * 2 + half;
        int i11 = (zr1 + yr1 + xc + PBASE) * 2 + half;

        float4 A = base[i00];
        float4 B = base[i01];
        float4 C = base[i10];
        float4 D = base[i11];

        float dv[4];
        dv[0] = A.x*c00 + B.x*c01 + C.x*c10 + D.x*c11;
        dv[1] = A.y*c00 + B.y*c01 + C.y*c10 + D.y*c11;
        dv[2] = A.z*c00 + B.z*c01 + C.z*c10 + D.z*c11;
        dv[3] = A.w*c00 + B.w*c01 + C.w*c10 + D.w*c11;

        const float* wp = &sw[(k * 8 + half * 4) * 16];
#pragma unroll
        for (int ci = 0; ci < 4; ci++) {
#pragma unroll
            for (int co = 0; co < 16; co++)
                acc[co] = fmaf(dv[ci], wp[ci * 16 + co], acc[co]);
        }
    }

    // combine channel halves within the pair
#pragma unroll
    for (int co = 0; co < 16; co++)
        acc[co] += __shfl_xor_sync(0xFFFFFFFFu, acc[co], 1);

    // store: even lane writes co 0-7, odd lane co 8-15
#pragma unroll
    for (int c = 0; c < 8; c++) {
        int co = half * 8 + c;
        g_conv[co * V + v] = acc[co];
    }

    // GN stats: both pair-threads hold identical acc -> scale by 0.5
    int lane = tid & 31;
#pragma unroll
    for (int g = 0; g < 4; g++) {
        float s = acc[4 * g] + acc[4 * g + 1] + acc[4 * g + 2] + acc[4 * g + 3];
        float q = acc[4 * g] * acc[4 * g] + acc[4 * g + 1] * acc[4 * g + 1]
                + acc[4 * g + 2] * acc[4 * g + 2] + acc[4 * g + 3] * acc[4 * g + 3];
#pragma unroll
        for (int off = 16; off; off >>= 1) {
            s += __shfl_down_sync(0xFFFFFFFFu, s, off);
            q += __shfl_down_sync(0xFFFFFFFFu, q, off);
        }
        if (lane == 0) {
            atomicAdd(&g_gsum[g], 0.5f * s);
            atomicAdd(&g_gsq[g], 0.5f * q);
        }
    }
}

// ---------------- kernel 5: finalize GN ----------------
__global__ void k_gn_final(const float* __restrict__ gng, const float* __restrict__ gnb) {
    int co = threadIdx.x;
    if (co < 16) {
        int g = co >> 2;
        float inv = 1.0f / (4.0f * (float)V);
        float mean = g_gsum[g] * inv;
        float var  = g_gsq[g] * inv - mean * mean;
        float s = gng[co] * rsqrtf(var + EPSV);
        g_gns[co] = s;
        g_gnt[co] = gnb[co] - mean * s;
    }
}

// ---------------- kernel 6: apply GN + ReLU (vectorized) ----------------
__global__ void k_gn_apply(float* __restrict__ out) {
    int i4 = blockIdx.x * 256 + threadIdx.x;
    int co = (i4 * 4) >> 18;
    float s = g_gns[co], t = g_gnt[co];
    float4 a = reinterpret_cast<const float4*>(g_conv)[i4];
    float4 r;
    r.x = fmaxf(fmaf(a.x, s, t), 0.f);
    r.y = fmaxf(fmaf(a.y, s, t), 0.f);
    r.z = fmaxf(fmaf(a.z, s, t), 0.f);
    r.w = fmaxf(fmaf(a.w, s, t), 0.f);
    reinterpret_cast<float4*>(out)[i4] = r;
}

// ---------------- launch ----------------
extern "C" void kernel_launch(void* const* d_in, const int* in_sizes, int n_in,
                              void* d_out, int out_size) {
    (void)in_sizes; (void)n_in; (void)out_size;
    const float* f    = (const float*)d_in[0];
    const float* offw = (const float*)d_in[1];
    const float* offb = (const float*)d_in[2];
    const float* bng  = (const float*)d_in[3];
    const float* bnb  = (const float*)d_in[4];
    const float* dcnw = (const float*)d_in[5];
    const float* dcnb = (const float*)d_in[6];
    const float* gng  = (const float*)d_in[7];
    const float* gnb  = (const float*)d_in[8];
    float* out = (float*)d_out;

    k_transpose<<<(PV + 255) / 256, 256>>>(f);
    k_conv_off<<<256, 256>>>(offw, offb);
    k_bn_final<<<1, 32>>>(bng, bnb);
    k_main<<<1024, 512>>>(dcnw, dcnb);
    k_gn_final<<<1, 32>>>(gng, gnb);
    k_gn_apply<<<4096, 256>>>(out);
}

// round 7
// speedup vs baseline: 5.5105x; 1.2760x over previous
#include <cuda_runtime.h>
#include <cuda_fp16.h>
#include <math.h>

#define V    262144         // 64^3
#define PD   66             // padded dim
#define PS   (PD*PD)        // 4356
#define PV   (PD*PD*PD)     // 287496
#define PBASE (PS + PD + 1) // offset of voxel (0,0,0) in padded volume
#define EPSV 1e-5f

// ---------------- scratch (__device__ globals; no allocation) ----------------
__device__ float  g_ft[PV * 8];      // zero-padded fp32 feat [66^3][8] (for conv_off)
__device__ float4 g_fth[PV];         // zero-padded fp16 feat [66^3][8 halves] (for gather)
__device__ float g_off[18 * V];
__device__ float g_conv[16 * V];
__device__ float g_bnsum[18];
__device__ float g_bnsq[18];
__device__ float g_bns[18];
__device__ float g_bnt[18];
__device__ float g_gsum[4];
__device__ float g_gsq[4];
__device__ float g_gns[16];
__device__ float g_gnt[16];

// ---------------- kernel 1: pad+transpose f -> fp32 & fp16 padded volumes ----------------
__global__ void k_transpose(const float* __restrict__ f) {
    int tid = threadIdx.x;
    if (blockIdx.x == 0 && tid < 22) {
        if (tid < 18) { g_bnsum[tid] = 0.f; g_bnsq[tid] = 0.f; }
        else          { g_gsum[tid - 18] = 0.f; g_gsq[tid - 18] = 0.f; }
    }
    int pv = blockIdx.x * blockDim.x + tid;
    if (pv >= PV) return;
    int z = pv / PS, r = pv % PS, y = r / PD, x = r % PD;
    float4 a = make_float4(0.f, 0.f, 0.f, 0.f), b = a;
    if (z >= 1 && z <= 64 && y >= 1 && y <= 64 && x >= 1 && x <= 64) {
        int v = (((z - 1) << 6) + (y - 1) << 6) + (x - 1);
        a.x = f[0 * V + v]; a.y = f[1 * V + v]; a.z = f[2 * V + v]; a.w = f[3 * V + v];
        b.x = f[4 * V + v]; b.y = f[5 * V + v]; b.z = f[6 * V + v]; b.w = f[7 * V + v];
    }
    float4* dst = reinterpret_cast<float4*>(g_ft);
    dst[pv * 2 + 0] = a;
    dst[pv * 2 + 1] = b;

    float4 hp;
    __half2* hh = reinterpret_cast<__half2*>(&hp);
    hh[0] = __floats2half2_rn(a.x, a.y);
    hh[1] = __floats2half2_rn(a.z, a.w);
    hh[2] = __floats2half2_rn(b.x, b.y);
    hh[3] = __floats2half2_rn(b.z, b.w);
    g_fth[pv] = hp;
}

// ---------------- kernel 2: offset conv3d, 4 voxels/thread, 2 passes of 9 oc ----------------
__global__ void __launch_bounds__(256, 2)
k_conv_off(const float* __restrict__ offw, const float* __restrict__ offb) {
    __shared__ float sw[27 * 18 * 8];   // [tap][oc][ci], tap = t9*3 + dx
    __shared__ int   srow[9];
    __shared__ float sbias[18];
    int tid = threadIdx.x;
    for (int i = tid; i < 3888; i += 256) {
        int oc = i / 216, r = i % 216, ci = r / 27, tap = r % 27;
        sw[(tap * 18 + oc) * 8 + ci] = offw[i];
    }
    if (tid < 9) {
        int dz = tid / 3 - 1, dy = tid % 3 - 1;
        srow[tid] = (dz * PS + dy * PD - 1) * 2;
    }
    if (tid < 18) sbias[tid] = offb[tid];
    __syncthreads();

    int t = blockIdx.x * 256 + tid;
    int h4 = (t & 15) << 2;
    int w  = (t >> 4) & 63;
    int d  = t >> 10;
    int pc = (d * PS + w * PD + h4 + PBASE) * 2;
    int v0 = t << 2;
    int lane = tid & 31;

    const float4* base = reinterpret_cast<const float4*>(g_ft);

#pragma unroll 1
    for (int ocb = 0; ocb < 18; ocb += 9) {
        float acc[9][4];
#pragma unroll
        for (int o = 0; o < 9; o++) {
            float b = sbias[ocb + o];
            acc[o][0] = b; acc[o][1] = b; acc[o][2] = b; acc[o][3] = b;
        }

#pragma unroll 1
        for (int t9 = 0; t9 < 9; t9++) {
            int rb = pc + srow[t9];
            float4 in[12];
#pragma unroll
            for (int j = 0; j < 12; j++) in[j] = base[rb + j];

            const float* swt = &sw[t9 * 432];
#pragma unroll
            for (int o = 0; o < 9; o++) {
#pragma unroll
                for (int dx = 0; dx < 3; dx++) {
                    const float4* wp = reinterpret_cast<const float4*>(
                        &swt[dx * 144 + (ocb + o) * 8]);
                    float4 w0 = wp[0], w1 = wp[1];
#pragma unroll
                    for (int vx = 0; vx < 4; vx++) {
                        float4 a  = in[2 * (vx + dx)];
                        float4 b2 = in[2 * (vx + dx) + 1];
                        float s = acc[o][vx];
                        s = fmaf(a.x,  w0.x, s); s = fmaf(a.y,  w0.y, s);
                        s = fmaf(a.z,  w0.z, s); s = fmaf(a.w,  w0.w, s);
                        s = fmaf(b2.x, w1.x, s); s = fmaf(b2.y, w1.y, s);
                        s = fmaf(b2.z, w1.z, s); s = fmaf(b2.w, w1.w, s);
                        acc[o][vx] = s;
                    }
                }
            }
        }

#pragma unroll
        for (int o = 0; o < 9; o++) {
            int j = ocb + o;
            float4 st = make_float4(acc[o][0], acc[o][1], acc[o][2], acc[o][3]);
            *reinterpret_cast<float4*>(&g_off[j * V + v0]) = st;
            float s = st.x + st.y + st.z + st.w;
            float q = st.x*st.x + st.y*st.y + st.z*st.z + st.w*st.w;
#pragma unroll
            for (int off = 16; off; off >>= 1) {
                s += __shfl_down_sync(0xFFFFFFFFu, s, off);
                q += __shfl_down_sync(0xFFFFFFFFu, q, off);
            }
            if (lane == 0) {
                atomicAdd(&g_bnsum[j], s);
                atomicAdd(&g_bnsq[j], q);
            }
        }
    }
}

// ---------------- kernel 3: finalize BN ----------------
__global__ void k_bn_final(const float* __restrict__ bng, const float* __restrict__ bnb) {
    int j = threadIdx.x;
    if (j < 18) {
        float mean = g_bnsum[j] * (1.0f / V);
        float var  = g_bnsq[j] * (1.0f / V) - mean * mean;
        float s = bng[j] * rsqrtf(var + EPSV);
        g_bns[j] = s;
        g_bnt[j] = bnb[j] - mean * s;
    }
}

// ---------------- kernel 4: BN+tanh, cumsum, fp16 4-corner gather, dcn conv, GN stats ----------------
__global__ void __launch_bounds__(256, 2)
k_main(const float* __restrict__ dcnw, const float* __restrict__ dcnb) {
    __shared__ float sw[16 * 8 * 9];   // [k][ci][co]
    __shared__ float sb[16];
    int tid = threadIdx.x;
    for (int i = tid; i < 1152; i += 256) {
        int co = i / 72, r = i % 72, ci = r / 9, k = r % 9;
        sw[(k * 8 + ci) * 16 + co] = dcnw[i];
    }
    if (tid < 16) sb[tid] = dcnb[tid];
    __syncthreads();

    int v = blockIdx.x * 256 + tid;
    int h = v & 63, w = (v >> 6) & 63, d = v >> 12;

    float zo[9], yo[9];
#pragma unroll
    for (int j = 0; j < 9; j++)
        zo[j] = tanhf(fmaf(g_off[j * V + v], g_bns[j], g_bnt[j]));
#pragma unroll
    for (int j = 0; j < 9; j++)
        yo[j] = tanhf(fmaf(g_off[(9 + j) * V + v], g_bns[9 + j], g_bnt[9 + j]));

#pragma unroll
    for (int k = 5; k < 9; k++) { zo[k] += zo[k - 1]; yo[k] += yo[k - 1]; }
#pragma unroll
    for (int k = 3; k >= 0; k--) { zo[k] += zo[k + 1]; yo[k] += yo[k + 1]; }

    float acc[16];
#pragma unroll
    for (int co = 0; co < 16; co++) acc[co] = sb[co];

#pragma unroll
    for (int k = 0; k < 9; k++) {
        float zf = (float)d + zo[k];
        float yf = (float)w + yo[k];
        int   xi = h + k - 4;
        float valid = ((unsigned)xi < 63u) ? 1.f : 0.f;
        int   xc = min(max(xi, 0), 63);

        int zb = (int)floorf(zf);
        int yb = (int)floorf(yf);
        int z0 = min(max(zb, 0), 63),  z1 = min(max(zb + 1, 0), 63);
        int y0 = min(max(yb, 0), 63),  y1 = min(max(yb + 1, 0), 63);

        float wz0 = (float)z1 - zf, wz1 = zf - (float)z0;
        float wy0 = (float)y1 - yf, wy1 = yf - (float)y0;

        __half2 c00 = __float2half2_rn(wz0 * wy0 * valid);
        __half2 c01 = __float2half2_rn(wz0 * wy1 * valid);
        __half2 c10 = __float2half2_rn(wz1 * wy0 * valid);
        __half2 c11 = __float2half2_rn(wz1 * wy1 * valid);

        int zr0 = z0 * PS, zr1 = z1 * PS;
        int yr0 = y0 * PD, yr1 = y1 * PD;
        float4 A = g_fth[zr0 + yr0 + xc + PBASE];
        float4 B = g_fth[zr0 + yr1 + xc + PBASE];
        float4 C = g_fth[zr1 + yr0 + xc + PBASE];
        float4 D = g_fth[zr1 + yr1 + xc + PBASE];
        const __half2* Ah = reinterpret_cast<const __half2*>(&A);
        const __half2* Bh = reinterpret_cast<const __half2*>(&B);
        const __half2* Ch = reinterpret_cast<const __half2*>(&C);
        const __half2* Dh = reinterpret_cast<const __half2*>(&D);

        float dv[8];
#pragma unroll
        for (int j = 0; j < 4; j++) {
            __half2 s = __hmul2(Ah[j], c00);
            s = __hfma2(Bh[j], c01, s);
            s = __hfma2(Ch[j], c10, s);
            s = __hfma2(Dh[j], c11, s);
            float2 fs = __half22float2(s);
            dv[2 * j]     = fs.x;
            dv[2 * j + 1] = fs.y;
        }

        const float* wp = &sw[(k * 8) * 16];
#pragma unroll
        for (int ci = 0; ci < 8; ci++) {
#pragma unroll
            for (int co = 0; co < 16; co++)
                acc[co] = fmaf(dv[ci], wp[ci * 16 + co], acc[co]);
        }
    }

#pragma unroll
    for (int co = 0; co < 16; co++) g_conv[co * V + v] = acc[co];

    int lane = tid & 31;
#pragma unroll
    for (int g = 0; g < 4; g++) {
        float s = acc[4 * g] + acc[4 * g + 1] + acc[4 * g + 2] + acc[4 * g + 3];
        float q = acc[4 * g] * acc[4 * g] + acc[4 * g + 1] * acc[4 * g + 1]
                + acc[4 * g + 2] * acc[4 * g + 2] + acc[4 * g + 3] * acc[4 * g + 3];
#pragma unroll
        for (int off = 16; off; off >>= 1) {
            s += __shfl_down_sync(0xFFFFFFFFu, s, off);
            q += __shfl_down_sync(0xFFFFFFFFu, q, off);
        }
        if (lane == 0) {
            atomicAdd(&g_gsum[g], s);
            atomicAdd(&g_gsq[g], q);
        }
    }
}

// ---------------- kernel 5: finalize GN ----------------
__global__ void k_gn_final(const float* __restrict__ gng, const float* __restrict__ gnb) {
    int co = threadIdx.x;
    if (co < 16) {
        int g = co >> 2;
        float inv = 1.0f / (4.0f * (float)V);
        float mean = g_gsum[g] * inv;
        float var  = g_gsq[g] * inv - mean * mean;
        float s = gng[co] * rsqrtf(var + EPSV);
        g_gns[co] = s;
        g_gnt[co] = gnb[co] - mean * s;
    }
}

// ---------------- kernel 6: apply GN + ReLU (vectorized) ----------------
__global__ void k_gn_apply(float* __restrict__ out) {
    int i4 = blockIdx.x * 256 + threadIdx.x;
    int co = (i4 * 4) >> 18;
    float s = g_gns[co], t = g_gnt[co];
    float4 a = reinterpret_cast<const float4*>(g_conv)[i4];
    float4 r;
    r.x = fmaxf(fmaf(a.x, s, t), 0.f);
    r.y = fmaxf(fmaf(a.y, s, t), 0.f);
    r.z = fmaxf(fmaf(a.z, s, t), 0.f);
    r.w = fmaxf(fmaf(a.w, s, t), 0.f);
    reinterpret_cast<float4*>(out)[i4] = r;
}

// ---------------- launch ----------------
extern "C" void kernel_launch(void* const* d_in, const int* in_sizes, int n_in,
                              void* d_out, int out_size) {
    (void)in_sizes; (void)n_in; (void)out_size;
    const float* f    = (const float*)d_in[0];
    const float* offw = (const float*)d_in[1];
    const float* offb = (const float*)d_in[2];
    const float* bng  = (const float*)d_in[3];
    const float* bnb  = (const float*)d_in[4];
    const float* dcnw = (const float*)d_in[5];
    const float* dcnb = (const float*)d_in[6];
    const float* gng  = (const float*)d_in[7];
    const float* gnb  = (const float*)d_in[8];
    float* out = (float*)d_out;

    k_transpose<<<(PV + 255) / 256, 256>>>(f);
    k_conv_off<<<256, 256>>>(offw, offb);
    k_bn_final<<<1, 32>>>(bng, bnb);
    k_main<<<1024, 256>>>(dcnw, dcnb);
    k_gn_final<<<1, 32>>>(gng, gnb);
    k_gn_apply<<<4096, 256>>>(out);
}